// round 15
// baseline (speedup 1.0000x reference)
#include <cuda_runtime.h>
#include <cuda_fp16.h>
#include <cuda_bf16.h>
#include <math.h>
#include <stdint.h>

#define NMAX 100000
#define EMAX 3200000
#define FIN  512
#define HID  256
#define NC   40

// ---------------- device scratch (static: no allocation) ----------------
__device__ int   g_is64;                  // edge_index dtype flag (1 = int64)
__device__ int   g_deg[NMAX];
__device__ float g_dinv[NMAX];
__device__ int   g_off[NMAX + 1];
__device__ int   g_cur[NMAX];
__device__ int   g_bsum[128];
__device__ int   g_bbase[128];
__device__ int   g_esrc[EMAX];
__device__ __align__(16) __nv_bfloat16 g_w1hi[HID * FIN];  // W1^T [256][512] bf16 hi
__device__ __align__(16) __nv_bfloat16 g_w1lo[HID * FIN];  // W1^T [256][512] bf16 lo
__device__ __align__(16) __half g_y1h[(size_t)NMAX * HID]; // dinv-scaled x@W1 (fp16 msgs)
__device__ __align__(16) __half g_hh [(size_t)NMAX * HID]; // layer-1 output (relu, fp16)
__device__ __align__(16) __half g_y2h[(size_t)NMAX * NC];  // dinv-scaled h@W2 (fp16 msgs)

// ---------------- helpers ----------------
__device__ __forceinline__ uint32_t smem_to_u32(const void* p) {
    uint32_t a;
    asm("{ .reg .u64 t; cvta.to.shared.u64 t, %1; cvt.u32.u64 %0, t; }"
        : "=r"(a) : "l"(p));
    return a;
}
__device__ __forceinline__ uint32_t sw128(uint32_t off) {
    return off ^ ((off >> 3) & 0x70);
}
__device__ __forceinline__ void ldm_x4(uint32_t& r0, uint32_t& r1,
                                       uint32_t& r2, uint32_t& r3, uint32_t a) {
    asm volatile("ldmatrix.sync.aligned.m8n8.x4.shared.b16 {%0,%1,%2,%3}, [%4];"
                 : "=r"(r0), "=r"(r1), "=r"(r2), "=r"(r3) : "r"(a));
}
__device__ __forceinline__ void ldm_x2(uint32_t& r0, uint32_t& r1, uint32_t a) {
    asm volatile("ldmatrix.sync.aligned.m8n8.x2.shared.b16 {%0,%1}, [%2];"
                 : "=r"(r0), "=r"(r1) : "r"(a));
}
__device__ __forceinline__ void mma_bf16(float* c, const uint32_t* a,
                                         const uint32_t* b) {
    asm volatile(
        "mma.sync.aligned.m16n8k16.row.col.f32.bf16.bf16.f32 "
        "{%0,%1,%2,%3}, {%4,%5,%6,%7}, {%8,%9}, {%0,%1,%2,%3};"
        : "+f"(c[0]), "+f"(c[1]), "+f"(c[2]), "+f"(c[3])
        : "r"(a[0]), "r"(a[1]), "r"(a[2]), "r"(a[3]), "r"(b[0]), "r"(b[1]));
}

// ---------------- edge index access (dtype-robust) ----------------
__device__ __forceinline__ int edge_at(const void* ei, int i) {
    if (g_is64) return (int)((const long long*)ei)[i];
    return ((const int*)ei)[i];
}

// ---------------- setup: zero degree + dtype detect (fused) ----------------
__global__ void k_zero_detect(const void* ei, int n) {
    int i = blockIdx.x * blockDim.x + threadIdx.x;
    if (i < n) g_deg[i] = 0;
    if (i == 0) {
        const int* w = (const int*)ei;
        int is64 = 1;
        for (int k = 0; k < 64; k++) {
            int lo = w[2 * k], hi = w[2 * k + 1];
            if (hi != 0 || lo < 0 || lo >= n) { is64 = 0; break; }
        }
        g_is64 = is64;
    }
}

__global__ void k_hist(const void* __restrict__ ei, int E) {
    int e = blockIdx.x * blockDim.x + threadIdx.x;
    if (e < E) atomicAdd(&g_deg[edge_at(ei, E + e)], 1);
}

// W1 [512][256] fp32 -> g_w1hi/g_w1lo [256][512] bf16 (K-major, transposed)
__global__ void k_wprep(const float* __restrict__ W1) {
    int idx = blockIdx.x * blockDim.x + threadIdx.x;   // 0 .. 256*512-1
    if (idx < HID * FIN) {
        int n = idx >> 9, k = idx & 511;
        float w = W1[(size_t)k * HID + n];
        __nv_bfloat16 hi = __float2bfloat16(w);
        __nv_bfloat16 lo = __float2bfloat16(w - __bfloat162float(hi));
        g_w1hi[idx] = hi;
        g_w1lo[idx] = lo;
    }
}

// ---------------- exclusive scan of g_deg -> g_off (+dinv fused) ----------------
__global__ void k_scan1(int n) {
    __shared__ int sdata[256];
    int b = blockIdx.x, t = threadIdx.x;
    int base = b * 1024 + t * 4;
    int v0 = (base + 0 < n) ? g_deg[base + 0] : 0;
    int v1 = (base + 1 < n) ? g_deg[base + 1] : 0;
    int v2 = (base + 2 < n) ? g_deg[base + 2] : 0;
    int v3 = (base + 3 < n) ? g_deg[base + 3] : 0;
    // fused dinv
    if (base + 0 < n) g_dinv[base + 0] = rsqrtf((float)(v0 + 1));
    if (base + 1 < n) g_dinv[base + 1] = rsqrtf((float)(v1 + 1));
    if (base + 2 < n) g_dinv[base + 2] = rsqrtf((float)(v2 + 1));
    if (base + 3 < n) g_dinv[base + 3] = rsqrtf((float)(v3 + 1));
    int tsum = v0 + v1 + v2 + v3;
    sdata[t] = tsum;
    __syncthreads();
    for (int off = 1; off < 256; off <<= 1) {
        int x = 0;
        if (t >= off) x = sdata[t - off];
        __syncthreads();
        sdata[t] += x;
        __syncthreads();
    }
    int run = sdata[t] - tsum;
    if (base + 0 < n) { g_off[base + 0] = run; run += v0; }
    if (base + 1 < n) { g_off[base + 1] = run; run += v1; }
    if (base + 2 < n) { g_off[base + 2] = run; run += v2; }
    if (base + 3 < n) { g_off[base + 3] = run; }
    if (t == 255) g_bsum[b] = sdata[255];
}

__global__ void k_scan2(int nb) {
    __shared__ int s[128];
    int t = threadIdx.x;
    int v = (t < nb) ? g_bsum[t] : 0;
    s[t] = v;
    __syncthreads();
    for (int off = 1; off < 128; off <<= 1) {
        int x = 0;
        if (t >= off) x = s[t - off];
        __syncthreads();
        s[t] += x;
        __syncthreads();
    }
    g_bbase[t] = s[t] - v;
}

__global__ void k_scan3(int n, int E) {
    int i = blockIdx.x * blockDim.x + threadIdx.x;
    if (i < n) {
        int o = g_off[i] + g_bbase[i >> 10];
        g_off[i] = o;
        g_cur[i] = o;
    }
    if (i == 0) g_off[n] = E;
}

__global__ void k_fill(const void* __restrict__ ei, int E) {
    int e = blockIdx.x * blockDim.x + threadIdx.x;
    if (e < E) {
        int r = edge_at(ei, e);          // source
        int c = edge_at(ei, E + e);      // target
        int pos = atomicAdd(&g_cur[c], 1);
        g_esrc[pos] = r;
    }
}

// ---------------- GEMM1 (mma.sync bf16 3-term, double-buffered, occ 2) ----------------
// CTA tile 64x128, 8 warps (2x4), warp tile 32x32, BK=64 bf16.
// Stage = 48KB (A hi/lo 16KB + B hi/lo 32KB), dbuf 96KB -> 2 CTAs/SM (16 warps).
// grid = (2 colblocks, rowblocks): adjacent CTAs share the A row-chunk in L2.
#define G1_AHI 0
#define G1_ALO 8192
#define G1_BHI 16384
#define G1_BLO 32768
#define G1_STAGE 49152
#define G1_TOT (2 * G1_STAGE)

__global__ __launch_bounds__(256, 2) void k_mma_gemm1(const float* __restrict__ A, int M) {
    extern __shared__ char smem[];
    uint32_t sb = smem_to_u32(smem);
    int tid  = threadIdx.x;
    int wid  = tid >> 5;
    int lane = tid & 31;
    int row0 = blockIdx.y * 64;
    int col0 = blockIdx.x * 128;
    int warp_m = wid & 1;          // 0/1 -> 32 rows each
    int warp_n = wid >> 1;         // 0..3 -> 32 cols each

    // ldmatrix per-lane address components
    int a_sel   = lane >> 3;                     // 0..3
    int a_row16 = (lane & 7) + ((a_sel & 1) << 3);
    int a_seg   = a_sel >> 1;                    // 0/1 (k half)
    int b_sel   = (lane >> 3) & 1;               // 0/1 (k half)
    int b_row   = lane & 7;

    float acc[2][4][4];
#pragma unroll
    for (int mi = 0; mi < 2; mi++)
#pragma unroll
        for (int ni = 0; ni < 4; ni++)
#pragma unroll
            for (int q = 0; q < 4; q++) acc[mi][ni][q] = 0.f;

    const char* w1hi = (const char*)g_w1hi;
    const char* w1lo = (const char*)g_w1lo;

    // ---- prefetch registers ----
    float4 av[4];
    uint4  bhv[4], blv[4];

    auto load_regs = [&](int k0) {
#pragma unroll
        for (int i = 0; i < 4; i++) {
            int li = tid + i * 256;                // 0..1023
            int r = li >> 4, c4 = li & 15;         // r 0..63
            int gr = row0 + r;
            av[i] = (gr < M)
                ? *(const float4*)(A + (size_t)gr * FIN + k0 + c4 * 4)
                : make_float4(0.f, 0.f, 0.f, 0.f);
        }
#pragma unroll
        for (int i = 0; i < 4; i++) {
            int li = tid + i * 256;                // 0..1023
            int r = li >> 3, seg = li & 7;         // r 0..127
            size_t gsrc = (size_t)(col0 + r) * (FIN * 2) + (size_t)k0 * 2 + seg * 16;
            bhv[i] = *(const uint4*)(w1hi + gsrc);
            blv[i] = *(const uint4*)(w1lo + gsrc);
        }
    };

    auto store_smem = [&](int so) {
#pragma unroll
        for (int i = 0; i < 4; i++) {
            int li = tid + i * 256;
            int r = li >> 4, c4 = li & 15;
            float4 v = av[i];
            __nv_bfloat162 h01 = make_bfloat162(__float2bfloat16(v.x), __float2bfloat16(v.y));
            __nv_bfloat162 h23 = make_bfloat162(__float2bfloat16(v.z), __float2bfloat16(v.w));
            __nv_bfloat162 l01 = make_bfloat162(
                __float2bfloat16(v.x - __bfloat162float(h01.x)),
                __float2bfloat16(v.y - __bfloat162float(h01.y)));
            __nv_bfloat162 l23 = make_bfloat162(
                __float2bfloat16(v.z - __bfloat162float(h23.x)),
                __float2bfloat16(v.w - __bfloat162float(h23.y)));
            uint32_t off = sw128((uint32_t)(r * 128 + c4 * 8));
            *(__nv_bfloat162*)(smem + so + G1_AHI + off)     = h01;
            *(__nv_bfloat162*)(smem + so + G1_AHI + off + 4) = h23;
            *(__nv_bfloat162*)(smem + so + G1_ALO + off)     = l01;
            *(__nv_bfloat162*)(smem + so + G1_ALO + off + 4) = l23;
        }
#pragma unroll
        for (int i = 0; i < 4; i++) {
            int li = tid + i * 256;
            int r = li >> 3, seg = li & 7;
            uint32_t off = sw128((uint32_t)(r * 128 + seg * 16));
            *(uint4*)(smem + so + G1_BHI + off) = bhv[i];
            *(uint4*)(smem + so + G1_BLO + off) = blv[i];
        }
    };

    load_regs(0);
    store_smem(0);
    __syncthreads();

    for (int c = 0; c < FIN / 64; c++) {          // 8 chunks of K=64
        int cur = (c & 1) * G1_STAGE;
        if (c < 7) load_regs((c + 1) * 64);        // global prefetch (overlaps mma)

        // ---- compute: 4 k16 steps from stage cur ----
#pragma unroll
        for (int ks = 0; ks < 4; ks++) {
            uint32_t ahi[2][4], alo[2][4], bhi[4][2], blo[4][2];
#pragma unroll
            for (int mi = 0; mi < 2; mi++) {
                int row = warp_m * 32 + mi * 16 + a_row16;
                uint32_t off = sw128((uint32_t)(row * 128 + (ks * 2 + a_seg) * 16));
                ldm_x4(ahi[mi][0], ahi[mi][1], ahi[mi][2], ahi[mi][3],
                       sb + cur + G1_AHI + off);
                ldm_x4(alo[mi][0], alo[mi][1], alo[mi][2], alo[mi][3],
                       sb + cur + G1_ALO + off);
            }
#pragma unroll
            for (int ni = 0; ni < 4; ni++) {
                int rn = warp_n * 32 + ni * 8 + b_row;
                uint32_t off = sw128((uint32_t)(rn * 128 + (ks * 2 + b_sel) * 16));
                ldm_x2(bhi[ni][0], bhi[ni][1], sb + cur + G1_BHI + off);
                ldm_x2(blo[ni][0], blo[ni][1], sb + cur + G1_BLO + off);
            }
#pragma unroll
            for (int mi = 0; mi < 2; mi++)
#pragma unroll
                for (int ni = 0; ni < 4; ni++) {
                    mma_bf16(acc[mi][ni], ahi[mi], bhi[ni]);
                    mma_bf16(acc[mi][ni], ahi[mi], blo[ni]);
                    mma_bf16(acc[mi][ni], alo[mi], bhi[ni]);
                }
        }

        if (c < 7) store_smem(((c + 1) & 1) * G1_STAGE);
        __syncthreads();
    }

    // ---- epilogue: dinv scale + fp16 store ----
#pragma unroll
    for (int mi = 0; mi < 2; mi++) {
        int r0 = row0 + warp_m * 32 + mi * 16 + (lane >> 2);
        int r1 = r0 + 8;
        float d0 = (r0 < M) ? g_dinv[r0] : 0.f;
        float d1 = (r1 < M) ? g_dinv[r1] : 0.f;
#pragma unroll
        for (int ni = 0; ni < 4; ni++) {
            int cc = col0 + warp_n * 32 + ni * 8 + (lane & 3) * 2;
            if (r0 < M)
                *(__half2*)&g_y1h[(size_t)r0 * HID + cc] =
                    __floats2half2_rn(d0 * acc[mi][ni][0], d0 * acc[mi][ni][1]);
            if (r1 < M)
                *(__half2*)&g_y1h[(size_t)r1 * HID + cc] =
                    __floats2half2_rn(d1 * acc[mi][ni][2], d1 * acc[mi][ni][3]);
        }
    }
}

// ---------------- Aggregation 1: h = relu(dinv*(sum y1[src] + y1[c]) + b1) ----------------
// one warp per node; lane owns features [8*lane, 8*lane+8) -> one 16B load/edge.
__global__ void k_agg1(const float* __restrict__ b1, int M) {
    int gid  = blockIdx.x * blockDim.x + threadIdx.x;
    int c    = gid >> 5;
    int lane = gid & 31;
    if (c >= M) return;

    const uint4* Y = (const uint4*)g_y1h;    // 32 uint4 per 256-half row
    float a[8];
#pragma unroll
    for (int j = 0; j < 8; j++) a[j] = 0.f;

    int s0 = g_off[c], s1 = g_off[c + 1];
    for (int i = s0; i < s1; i++) {
        int s = g_esrc[i];
        uint4 v = __ldg(Y + (size_t)s * 32 + lane);
        const __half2* h2 = (const __half2*)&v;
#pragma unroll
        for (int j = 0; j < 4; j++) {
            float2 f = __half22float2(h2[j]);
            a[2 * j]     += f.x;
            a[2 * j + 1] += f.y;
        }
    }
    {   // self loop
        uint4 v = __ldg(Y + (size_t)c * 32 + lane);
        const __half2* h2 = (const __half2*)&v;
#pragma unroll
        for (int j = 0; j < 4; j++) {
            float2 f = __half22float2(h2[j]);
            a[2 * j]     += f.x;
            a[2 * j + 1] += f.y;
        }
    }
    float d = g_dinv[c];
    float4 bb0 = *(const float4*)(b1 + lane * 8);
    float4 bb1 = *(const float4*)(b1 + lane * 8 + 4);
    __half2 o[4];
    o[0] = __floats2half2_rn(fmaxf(d * a[0] + bb0.x, 0.f), fmaxf(d * a[1] + bb0.y, 0.f));
    o[1] = __floats2half2_rn(fmaxf(d * a[2] + bb0.z, 0.f), fmaxf(d * a[3] + bb0.w, 0.f));
    o[2] = __floats2half2_rn(fmaxf(d * a[4] + bb1.x, 0.f), fmaxf(d * a[5] + bb1.y, 0.f));
    o[3] = __floats2half2_rn(fmaxf(d * a[6] + bb1.z, 0.f), fmaxf(d * a[7] + bb1.w, 0.f));
    *(uint4*)&g_hh[(size_t)c * HID + lane * 8] = *(uint4*)o;
}

// ---------------- GEMM2: y2 = dinv .* (h @ W2)   [M,256]x[256,40], fp16 in/out ----------------
__global__ __launch_bounds__(256) void k_sgemm2(const float* __restrict__ W2, int M) {
    __shared__ __align__(16) float hs[16][260];
    __shared__ __align__(16) float ws[16 * NC];
    int tid = threadIdx.x;
    int R0  = blockIdx.x * 256;
    int kv  = tid & 3;
    int rld = tid >> 2;
    int cg  = tid & 3;
    int rq  = tid >> 2;

    float acc[4][10];
#pragma unroll
    for (int i = 0; i < 4; i++)
#pragma unroll
        for (int j = 0; j < 10; j++) acc[i][j] = 0.f;

    for (int k0 = 0; k0 < HID; k0 += 16) {
#pragma unroll
        for (int p = 0; p < 4; p++) {
            int rr = rld + p * 64;
            int gr = R0 + rr;
            float2 f0 = make_float2(0.f, 0.f), f1 = f0;
            if (gr < M) {
                uint2 raw = *(const uint2*)&g_hh[(size_t)gr * HID + k0 + kv * 4];
                const __half2* h2 = (const __half2*)&raw;
                f0 = __half22float2(h2[0]);
                f1 = __half22float2(h2[1]);
            }
            hs[kv * 4 + 0][rr] = f0.x;
            hs[kv * 4 + 1][rr] = f0.y;
            hs[kv * 4 + 2][rr] = f1.x;
            hs[kv * 4 + 3][rr] = f1.y;
        }
        if (tid < 160) {
            const float* wp = W2 + (size_t)k0 * NC + tid * 4;
            ws[tid * 4 + 0] = wp[0];
            ws[tid * 4 + 1] = wp[1];
            ws[tid * 4 + 2] = wp[2];
            ws[tid * 4 + 3] = wp[3];
        }
        __syncthreads();

#pragma unroll
        for (int kk = 0; kk < 16; kk++) {
            float h0 = hs[kk][rq * 4 + 0];
            float h1 = hs[kk][rq * 4 + 1];
            float h2 = hs[kk][rq * 4 + 2];
            float h3 = hs[kk][rq * 4 + 3];
#pragma unroll
            for (int j = 0; j < 10; j++) {
                float w = ws[kk * NC + cg * 10 + j];
                acc[0][j] += h0 * w;
                acc[1][j] += h1 * w;
                acc[2][j] += h2 * w;
                acc[3][j] += h3 * w;
            }
        }
        __syncthreads();
    }

#pragma unroll
    for (int i = 0; i < 4; i++) {
        int r = R0 + rq * 4 + i;
        if (r < M) {
            float d = g_dinv[r];
            __half* yp = &g_y2h[(size_t)r * NC + cg * 10];
#pragma unroll
            for (int j = 0; j < 10; j++) yp[j] = __float2half_rn(d * acc[i][j]);
        }
    }
}

// ---------------- Aggregation 2 + bias + log_softmax ----------------
// one warp per node; lane l<20 owns cols {2l, 2l+1} via one half2 load/edge.
__global__ void k_agg2_softmax(const float* __restrict__ b2,
                               float* __restrict__ out, int M) {
    int gid  = blockIdx.x * blockDim.x + threadIdx.x;
    int c    = gid >> 5;
    int l    = gid & 31;
    if (c >= M) return;

    bool act = (l < 20);
    float ax = 0.f, ay = 0.f;
    int s0 = g_off[c], s1 = g_off[c + 1];
    for (int i = s0; i < s1; i++) {
        int s = g_esrc[i];
        if (act) {
            float2 f = __half22float2(
                __ldg((const __half2*)(g_y2h + (size_t)s * NC) + l));
            ax += f.x; ay += f.y;
        }
    }
    if (act) {
        float2 f = __half22float2(
            __ldg((const __half2*)(g_y2h + (size_t)c * NC) + l));
        ax += f.x; ay += f.y;
    }
    float d  = g_dinv[c];
    float v0 = act ? (d * ax + __ldg(b2 + 2 * l))     : -3.4e38f;
    float v1 = act ? (d * ay + __ldg(b2 + 2 * l + 1)) : -3.4e38f;

    float m = fmaxf(v0, v1);
#pragma unroll
    for (int o = 16; o; o >>= 1) m = fmaxf(m, __shfl_xor_sync(0xffffffffu, m, o));
    float e = act ? (expf(v0 - m) + expf(v1 - m)) : 0.f;
#pragma unroll
    for (int o = 16; o; o >>= 1) e += __shfl_xor_sync(0xffffffffu, e, o);
    float lse = m + logf(e);

    if (act) {
        out[(size_t)c * NC + 2 * l]     = v0 - lse;
        out[(size_t)c * NC + 2 * l + 1] = v1 - lse;
    }
}

// ---------------- launch ----------------
extern "C" void kernel_launch(void* const* d_in, const int* in_sizes, int n_in,
                              void* d_out, int out_size) {
    const float* x   = (const float*)d_in[0];
    const void*  ei  = d_in[1];               // edge_index: int32 OR int64 (detected)
    const float* W1  = (const float*)d_in[2];
    const float* b1  = (const float*)d_in[3];
    const float* W2  = (const float*)d_in[4];
    const float* b2  = (const float*)d_in[5];
    float*       out = (float*)d_out;

    int M = in_sizes[0] / FIN;   // 100000
    int E = in_sizes[1] / 2;     // 3200000

    int tb = 256;
    int gM = (M + tb - 1) / tb;
    int gE = (E + tb - 1) / tb;

    // setup: zero+detect, degree histogram, W1 prep
    k_zero_detect<<<gM, tb>>>(ei, M);
    k_hist<<<gE, tb>>>(ei, E);
    k_wprep<<<(HID * FIN + 255) / 256, 256>>>(W1);

    // CSR: scan (+dinv) + fill
    int NB = (M + 1023) / 1024;          // 98
    k_scan1<<<NB, 256>>>(M);
    k_scan2<<<1, 128>>>(NB);
    k_scan3<<<gM, tb>>>(M, E);
    k_fill<<<gE, tb>>>(ei, E);

    // layer 1: tensor-core GEMM (mma.sync, dbuf, 2 CTAs/SM) + CSR gather
    cudaFuncSetAttribute(k_mma_gemm1, cudaFuncAttributeMaxDynamicSharedMemorySize,
                         G1_TOT);
    dim3 g1(2, (M + 63) / 64);           // x = colblock (adjacent -> A reuse in L2)
    k_mma_gemm1<<<g1, 256, G1_TOT>>>(x, M);
    int gW = ((M * 32) + tb - 1) / tb;   // one warp per node
    k_agg1<<<gW, tb>>>(b1, M);

    // layer 2 + softmax
    k_sgemm2<<<(M + 255) / 256, 256>>>(W2, M);
    k_agg2_softmax<<<gW, tb>>>(b2, out, M);
}

// round 16
// speedup vs baseline: 1.0936x; 1.0936x over previous
#include <cuda_runtime.h>
#include <cuda_fp16.h>
#include <cuda_bf16.h>
#include <math.h>
#include <stdint.h>

#define NMAX 100000
#define EMAX 3200000
#define FIN  512
#define HID  256
#define NC   40

// ---------------- device scratch (static: no allocation) ----------------
__device__ int   g_is64;                  // edge_index dtype flag (1 = int64)
__device__ int   g_deg[NMAX];
__device__ float g_dinv[NMAX];
__device__ int   g_off[NMAX + 1];
__device__ int   g_cur[NMAX];
__device__ int   g_bsum[128];
__device__ int   g_bbase[128];
__device__ int   g_esrc[EMAX];
__device__ __align__(16) __nv_bfloat16 g_w1hi[HID * FIN];  // W1^T [256][512] bf16 hi
__device__ __align__(16) __nv_bfloat16 g_w1lo[HID * FIN];  // W1^T [256][512] bf16 lo
__device__ __align__(16) __half g_w2hi[NC * HID];          // W2^T [40][256] fp16 hi
__device__ __align__(16) __half g_w2lo[NC * HID];          // W2^T [40][256] fp16 lo
__device__ __align__(16) __half g_y1h[(size_t)NMAX * HID]; // dinv-scaled x@W1 (fp16 msgs)
__device__ __align__(16) __half g_hh [(size_t)NMAX * HID]; // layer-1 output (relu, fp16)
__device__ __align__(16) __half g_y2h[(size_t)NMAX * NC];  // dinv-scaled h@W2 (fp16 msgs)

// ---------------- helpers ----------------
__device__ __forceinline__ uint32_t smem_to_u32(const void* p) {
    uint32_t a;
    asm("{ .reg .u64 t; cvta.to.shared.u64 t, %1; cvt.u32.u64 %0, t; }"
        : "=r"(a) : "l"(p));
    return a;
}
__device__ __forceinline__ uint32_t sw128(uint32_t off) {
    return off ^ ((off >> 3) & 0x70);
}
// swizzle for 512B rows (bits[11:9] -> bits[6:4])
__device__ __forceinline__ uint32_t sw512(uint32_t off) {
    return off ^ ((off >> 5) & 0x70);
}
__device__ __forceinline__ void ldm_x4(uint32_t& r0, uint32_t& r1,
                                       uint32_t& r2, uint32_t& r3, uint32_t a) {
    asm volatile("ldmatrix.sync.aligned.m8n8.x4.shared.b16 {%0,%1,%2,%3}, [%4];"
                 : "=r"(r0), "=r"(r1), "=r"(r2), "=r"(r3) : "r"(a));
}
__device__ __forceinline__ void ldm_x2(uint32_t& r0, uint32_t& r1, uint32_t a) {
    asm volatile("ldmatrix.sync.aligned.m8n8.x2.shared.b16 {%0,%1}, [%2];"
                 : "=r"(r0), "=r"(r1) : "r"(a));
}
__device__ __forceinline__ void mma_bf16(float* c, const uint32_t* a,
                                         const uint32_t* b) {
    asm volatile(
        "mma.sync.aligned.m16n8k16.row.col.f32.bf16.bf16.f32 "
        "{%0,%1,%2,%3}, {%4,%5,%6,%7}, {%8,%9}, {%0,%1,%2,%3};"
        : "+f"(c[0]), "+f"(c[1]), "+f"(c[2]), "+f"(c[3])
        : "r"(a[0]), "r"(a[1]), "r"(a[2]), "r"(a[3]), "r"(b[0]), "r"(b[1]));
}
__device__ __forceinline__ void mma_f16(float* c, const uint32_t* a,
                                        const uint32_t* b) {
    asm volatile(
        "mma.sync.aligned.m16n8k16.row.col.f32.f16.f16.f32 "
        "{%0,%1,%2,%3}, {%4,%5,%6,%7}, {%8,%9}, {%0,%1,%2,%3};"
        : "+f"(c[0]), "+f"(c[1]), "+f"(c[2]), "+f"(c[3])
        : "r"(a[0]), "r"(a[1]), "r"(a[2]), "r"(a[3]), "r"(b[0]), "r"(b[1]));
}

// ---------------- edge index access (dtype-robust) ----------------
__device__ __forceinline__ int edge_at(const void* ei, int i) {
    if (g_is64) return (int)((const long long*)ei)[i];
    return ((const int*)ei)[i];
}

// ---------------- setup: zero degree + dtype detect (fused) ----------------
__global__ void k_zero_detect(const void* ei, int n) {
    int i = blockIdx.x * blockDim.x + threadIdx.x;
    if (i < n) g_deg[i] = 0;
    if (i == 0) {
        const int* w = (const int*)ei;
        int is64 = 1;
        for (int k = 0; k < 64; k++) {
            int lo = w[2 * k], hi = w[2 * k + 1];
            if (hi != 0 || lo < 0 || lo >= n) { is64 = 0; break; }
        }
        g_is64 = is64;
    }
}

__global__ void k_hist(const void* __restrict__ ei, int E) {
    int e = blockIdx.x * blockDim.x + threadIdx.x;
    if (e < E) atomicAdd(&g_deg[edge_at(ei, E + e)], 1);
}

// W1 [512][256] fp32 -> g_w1hi/g_w1lo [256][512] bf16 (K-major, transposed)
__global__ void k_wprep(const float* __restrict__ W1) {
    int idx = blockIdx.x * blockDim.x + threadIdx.x;   // 0 .. 256*512-1
    if (idx < HID * FIN) {
        int n = idx >> 9, k = idx & 511;
        float w = W1[(size_t)k * HID + n];
        __nv_bfloat16 hi = __float2bfloat16(w);
        __nv_bfloat16 lo = __float2bfloat16(w - __bfloat162float(hi));
        g_w1hi[idx] = hi;
        g_w1lo[idx] = lo;
    }
}

// W2 [256][40] fp32 -> g_w2hi/g_w2lo [40][256] fp16 (K-major, transposed)
__global__ void k_w2prep(const float* __restrict__ W2) {
    int idx = blockIdx.x * blockDim.x + threadIdx.x;   // 0 .. 40*256-1
    if (idx < NC * HID) {
        int n = idx >> 8, k = idx & 255;
        float w = W2[(size_t)k * NC + n];
        __half hi = __float2half_rn(w);
        __half lo = __float2half_rn(w - __half2float(hi));
        g_w2hi[idx] = hi;
        g_w2lo[idx] = lo;
    }
}

// ---------------- exclusive scan of g_deg -> g_off (+dinv fused) ----------------
__global__ void k_scan1(int n) {
    __shared__ int sdata[256];
    int b = blockIdx.x, t = threadIdx.x;
    int base = b * 1024 + t * 4;
    int v0 = (base + 0 < n) ? g_deg[base + 0] : 0;
    int v1 = (base + 1 < n) ? g_deg[base + 1] : 0;
    int v2 = (base + 2 < n) ? g_deg[base + 2] : 0;
    int v3 = (base + 3 < n) ? g_deg[base + 3] : 0;
    // fused dinv
    if (base + 0 < n) g_dinv[base + 0] = rsqrtf((float)(v0 + 1));
    if (base + 1 < n) g_dinv[base + 1] = rsqrtf((float)(v1 + 1));
    if (base + 2 < n) g_dinv[base + 2] = rsqrtf((float)(v2 + 1));
    if (base + 3 < n) g_dinv[base + 3] = rsqrtf((float)(v3 + 1));
    int tsum = v0 + v1 + v2 + v3;
    sdata[t] = tsum;
    __syncthreads();
    for (int off = 1; off < 256; off <<= 1) {
        int x = 0;
        if (t >= off) x = sdata[t - off];
        __syncthreads();
        sdata[t] += x;
        __syncthreads();
    }
    int run = sdata[t] - tsum;
    if (base + 0 < n) { g_off[base + 0] = run; run += v0; }
    if (base + 1 < n) { g_off[base + 1] = run; run += v1; }
    if (base + 2 < n) { g_off[base + 2] = run; run += v2; }
    if (base + 3 < n) { g_off[base + 3] = run; }
    if (t == 255) g_bsum[b] = sdata[255];
}

__global__ void k_scan2(int nb) {
    __shared__ int s[128];
    int t = threadIdx.x;
    int v = (t < nb) ? g_bsum[t] : 0;
    s[t] = v;
    __syncthreads();
    for (int off = 1; off < 128; off <<= 1) {
        int x = 0;
        if (t >= off) x = s[t - off];
        __syncthreads();
        s[t] += x;
        __syncthreads();
    }
    g_bbase[t] = s[t] - v;
}

__global__ void k_scan3(int n, int E) {
    int i = blockIdx.x * blockDim.x + threadIdx.x;
    if (i < n) {
        int o = g_off[i] + g_bbase[i >> 10];
        g_off[i] = o;
        g_cur[i] = o;
    }
    if (i == 0) g_off[n] = E;
}

__global__ void k_fill(const void* __restrict__ ei, int E) {
    int e = blockIdx.x * blockDim.x + threadIdx.x;
    if (e < E) {
        int r = edge_at(ei, e);          // source
        int c = edge_at(ei, E + e);      // target
        int pos = atomicAdd(&g_cur[c], 1);
        g_esrc[pos] = r;
    }
}

// ---------------- GEMM1 (mma.sync bf16 3-term, double-buffered) ----------------
// CTA tile 128x128, 8 warps (2x4), warp tile 64x32, BK=64 bf16.  (R11 config)
#define G1_AHI 0
#define G1_ALO 16384
#define G1_BHI 32768
#define G1_BLO 49152
#define G1_STAGE 65536
#define G1_TOT (2 * G1_STAGE)

__global__ __launch_bounds__(256, 1) void k_mma_gemm1(const float* __restrict__ A, int M) {
    extern __shared__ char smem[];
    uint32_t sb = smem_to_u32(smem);
    int tid  = threadIdx.x;
    int wid  = tid >> 5;
    int lane = tid & 31;
    int row0 = blockIdx.y * 128;
    int col0 = blockIdx.x * 128;
    int warp_m = wid & 1;          // 0/1 -> 64 rows each
    int warp_n = wid >> 1;         // 0..3 -> 32 cols each

    int a_sel   = lane >> 3;                     // 0..3
    int a_row16 = (lane & 7) + ((a_sel & 1) << 3);
    int a_seg   = a_sel >> 1;                    // 0/1 (k half)
    int b_sel   = (lane >> 3) & 1;               // 0/1 (k half)
    int b_row   = lane & 7;

    float acc[4][4][4];
#pragma unroll
    for (int mi = 0; mi < 4; mi++)
#pragma unroll
        for (int ni = 0; ni < 4; ni++)
#pragma unroll
            for (int q = 0; q < 4; q++) acc[mi][ni][q] = 0.f;

    const char* w1hi = (const char*)g_w1hi;
    const char* w1lo = (const char*)g_w1lo;

    float4 av[8];
    uint4  bhv[4], blv[4];

    auto load_regs = [&](int k0) {
#pragma unroll
        for (int i = 0; i < 8; i++) {
            int li = tid + i * 256;
            int r = li >> 4, c4 = li & 15;
            int gr = row0 + r;
            av[i] = (gr < M)
                ? *(const float4*)(A + (size_t)gr * FIN + k0 + c4 * 4)
                : make_float4(0.f, 0.f, 0.f, 0.f);
        }
#pragma unroll
        for (int i = 0; i < 4; i++) {
            int li = tid + i * 256;
            int r = li >> 3, seg = li & 7;
            size_t gsrc = (size_t)(col0 + r) * (FIN * 2) + (size_t)k0 * 2 + seg * 16;
            bhv[i] = *(const uint4*)(w1hi + gsrc);
            blv[i] = *(const uint4*)(w1lo + gsrc);
        }
    };

    auto store_smem = [&](int so) {
#pragma unroll
        for (int i = 0; i < 8; i++) {
            int li = tid + i * 256;
            int r = li >> 4, c4 = li & 15;
            float4 v = av[i];
            __nv_bfloat162 h01 = make_bfloat162(__float2bfloat16(v.x), __float2bfloat16(v.y));
            __nv_bfloat162 h23 = make_bfloat162(__float2bfloat16(v.z), __float2bfloat16(v.w));
            __nv_bfloat162 l01 = make_bfloat162(
                __float2bfloat16(v.x - __bfloat162float(h01.x)),
                __float2bfloat16(v.y - __bfloat162float(h01.y)));
            __nv_bfloat162 l23 = make_bfloat162(
                __float2bfloat16(v.z - __bfloat162float(h23.x)),
                __float2bfloat16(v.w - __bfloat162float(h23.y)));
            uint32_t off = sw128((uint32_t)(r * 128 + c4 * 8));
            *(__nv_bfloat162*)(smem + so + G1_AHI + off)     = h01;
            *(__nv_bfloat162*)(smem + so + G1_AHI + off + 4) = h23;
            *(__nv_bfloat162*)(smem + so + G1_ALO + off)     = l01;
            *(__nv_bfloat162*)(smem + so + G1_ALO + off + 4) = l23;
        }
#pragma unroll
        for (int i = 0; i < 4; i++) {
            int li = tid + i * 256;
            int r = li >> 3, seg = li & 7;
            uint32_t off = sw128((uint32_t)(r * 128 + seg * 16));
            *(uint4*)(smem + so + G1_BHI + off) = bhv[i];
            *(uint4*)(smem + so + G1_BLO + off) = blv[i];
        }
    };

    load_regs(0);
    store_smem(0);
    __syncthreads();

    for (int c = 0; c < FIN / 64; c++) {          // 8 chunks of K=64
        int cur = (c & 1) * G1_STAGE;
        if (c < 7) load_regs((c + 1) * 64);        // global prefetch (overlaps mma)

#pragma unroll
        for (int ks = 0; ks < 4; ks++) {
            uint32_t ahi[4][4], alo[4][4], bhi[4][2], blo[4][2];
#pragma unroll
            for (int mi = 0; mi < 4; mi++) {
                int row = warp_m * 64 + mi * 16 + a_row16;
                uint32_t off = sw128((uint32_t)(row * 128 + (ks * 2 + a_seg) * 16));
                ldm_x4(ahi[mi][0], ahi[mi][1], ahi[mi][2], ahi[mi][3],
                       sb + cur + G1_AHI + off);
                ldm_x4(alo[mi][0], alo[mi][1], alo[mi][2], alo[mi][3],
                       sb + cur + G1_ALO + off);
            }
#pragma unroll
            for (int ni = 0; ni < 4; ni++) {
                int rn = warp_n * 32 + ni * 8 + b_row;
                uint32_t off = sw128((uint32_t)(rn * 128 + (ks * 2 + b_sel) * 16));
                ldm_x2(bhi[ni][0], bhi[ni][1], sb + cur + G1_BHI + off);
                ldm_x2(blo[ni][0], blo[ni][1], sb + cur + G1_BLO + off);
            }
#pragma unroll
            for (int mi = 0; mi < 4; mi++)
#pragma unroll
                for (int ni = 0; ni < 4; ni++) {
                    mma_bf16(acc[mi][ni], ahi[mi], bhi[ni]);
                    mma_bf16(acc[mi][ni], ahi[mi], blo[ni]);
                    mma_bf16(acc[mi][ni], alo[mi], bhi[ni]);
                }
        }

        if (c < 7) store_smem(((c + 1) & 1) * G1_STAGE);
        __syncthreads();
    }

    // ---- epilogue: dinv scale + fp16 store ----
#pragma unroll
    for (int mi = 0; mi < 4; mi++) {
        int r0 = row0 + warp_m * 64 + mi * 16 + (lane >> 2);
        int r1 = r0 + 8;
        float d0 = (r0 < M) ? g_dinv[r0] : 0.f;
        float d1 = (r1 < M) ? g_dinv[r1] : 0.f;
#pragma unroll
        for (int ni = 0; ni < 4; ni++) {
            int cc = col0 + warp_n * 32 + ni * 8 + (lane & 3) * 2;
            if (r0 < M)
                *(__half2*)&g_y1h[(size_t)r0 * HID + cc] =
                    __floats2half2_rn(d0 * acc[mi][ni][0], d0 * acc[mi][ni][1]);
            if (r1 < M)
                *(__half2*)&g_y1h[(size_t)r1 * HID + cc] =
                    __floats2half2_rn(d1 * acc[mi][ni][2], d1 * acc[mi][ni][3]);
        }
    }
}

// ---------------- Aggregation 1: h = relu(dinv*(sum y1[src] + y1[c]) + b1) ----------------
__global__ void k_agg1(const float* __restrict__ b1, int M) {
    int gid  = blockIdx.x * blockDim.x + threadIdx.x;
    int c    = gid >> 5;
    int lane = gid & 31;
    if (c >= M) return;

    const uint4* Y = (const uint4*)g_y1h;    // 32 uint4 per 256-half row
    float a[8];
#pragma unroll
    for (int j = 0; j < 8; j++) a[j] = 0.f;

    int s0 = g_off[c], s1 = g_off[c + 1];
    for (int i = s0; i < s1; i++) {
        int s = g_esrc[i];
        uint4 v = __ldg(Y + (size_t)s * 32 + lane);
        const __half2* h2 = (const __half2*)&v;
#pragma unroll
        for (int j = 0; j < 4; j++) {
            float2 f = __half22float2(h2[j]);
            a[2 * j]     += f.x;
            a[2 * j + 1] += f.y;
        }
    }
    {   // self loop
        uint4 v = __ldg(Y + (size_t)c * 32 + lane);
        const __half2* h2 = (const __half2*)&v;
#pragma unroll
        for (int j = 0; j < 4; j++) {
            float2 f = __half22float2(h2[j]);
            a[2 * j]     += f.x;
            a[2 * j + 1] += f.y;
        }
    }
    float d = g_dinv[c];
    float4 bb0 = *(const float4*)(b1 + lane * 8);
    float4 bb1 = *(const float4*)(b1 + lane * 8 + 4);
    __half2 o[4];
    o[0] = __floats2half2_rn(fmaxf(d * a[0] + bb0.x, 0.f), fmaxf(d * a[1] + bb0.y, 0.f));
    o[1] = __floats2half2_rn(fmaxf(d * a[2] + bb0.z, 0.f), fmaxf(d * a[3] + bb0.w, 0.f));
    o[2] = __floats2half2_rn(fmaxf(d * a[4] + bb1.x, 0.f), fmaxf(d * a[5] + bb1.y, 0.f));
    o[3] = __floats2half2_rn(fmaxf(d * a[6] + bb1.z, 0.f), fmaxf(d * a[7] + bb1.w, 0.f));
    *(uint4*)&g_hh[(size_t)c * HID + lane * 8] = *(uint4*)o;
}

// ---------------- GEMM2 (mma.sync f16 2-term): y2 = dinv .* (h @ W2) ----------------
// h is exact fp16 (no split); W2 split fp16 hi/lo. CTA = 128 rows, 8 warps x m16.
// smem: h tile 64KB (512B rows, sw512) + W2^T hi/lo 40KB. occupancy 2.
#define G2_H   0
#define G2_BHI 65536
#define G2_BLO (65536 + 20480)
#define G2_TOT (65536 + 40960)

__global__ __launch_bounds__(256, 2) void k_mma_gemm2(int M) {
    extern __shared__ char smem[];
    uint32_t sb = smem_to_u32(smem);
    int tid  = threadIdx.x;
    int wid  = tid >> 5;
    int lane = tid & 31;
    int R0   = blockIdx.x * 128;

    int a_sel   = lane >> 3;
    int a_row16 = (lane & 7) + ((a_sel & 1) << 3);
    int a_seg   = a_sel >> 1;
    int b_sel   = (lane >> 3) & 1;
    int b_row   = lane & 7;

    // ---- load h tile: 128 rows x 256 fp16 (512B rows, sw512) ----
#pragma unroll
    for (int i = 0; i < 16; i++) {
        int idx = tid + i * 256;             // 0..4095 (16B units)
        int r = idx >> 5, u = idx & 31;
        int gr = R0 + r;
        uint4 v = make_uint4(0, 0, 0, 0);
        if (gr < M) v = *(const uint4*)&g_hh[(size_t)gr * HID + u * 8];
        *(uint4*)(smem + G2_H + sw512((uint32_t)(r * 512 + u * 16))) = v;
    }
    // ---- load W2^T hi/lo: 40 rows x 256 fp16 each ----
#pragma unroll
    for (int i = 0; i < 5; i++) {
        int idx = tid + i * 256;             // 0..1279
        int r = idx >> 5, u = idx & 31;
        uint32_t off = sw512((uint32_t)(r * 512 + u * 16));
        *(uint4*)(smem + G2_BHI + off) = *(const uint4*)&g_w2hi[(size_t)r * HID + u * 8];
        *(uint4*)(smem + G2_BLO + off) = *(const uint4*)&g_w2lo[(size_t)r * HID + u * 8];
    }
    __syncthreads();

    float acc[5][4];
#pragma unroll
    for (int ni = 0; ni < 5; ni++)
#pragma unroll
        for (int q = 0; q < 4; q++) acc[ni][q] = 0.f;

    // warp wid owns rows [wid*16, wid*16+16)
#pragma unroll
    for (int ks = 0; ks < 16; ks++) {
        uint32_t a[4];
        {
            int row = wid * 16 + a_row16;
            uint32_t off = sw512((uint32_t)(row * 512 + ks * 32 + a_seg * 16));
            ldm_x4(a[0], a[1], a[2], a[3], sb + G2_H + off);
        }
#pragma unroll
        for (int ni = 0; ni < 5; ni++) {
            int rn = ni * 8 + b_row;
            uint32_t off = sw512((uint32_t)(rn * 512 + ks * 32 + b_sel * 16));
            uint32_t bh[2], bl[2];
            ldm_x2(bh[0], bh[1], sb + G2_BHI + off);
            ldm_x2(bl[0], bl[1], sb + G2_BLO + off);
            mma_f16(acc[ni], a, bh);
            mma_f16(acc[ni], a, bl);
        }
    }

    // ---- epilogue: dinv scale + fp16 store to y2 ----
    int r0 = R0 + wid * 16 + (lane >> 2);
    int r1 = r0 + 8;
    float d0 = (r0 < M) ? g_dinv[r0] : 0.f;
    float d1 = (r1 < M) ? g_dinv[r1] : 0.f;
#pragma unroll
    for (int ni = 0; ni < 5; ni++) {
        int cc = ni * 8 + (lane & 3) * 2;
        if (r0 < M)
            *(__half2*)&g_y2h[(size_t)r0 * NC + cc] =
                __floats2half2_rn(d0 * acc[ni][0], d0 * acc[ni][1]);
        if (r1 < M)
            *(__half2*)&g_y2h[(size_t)r1 * NC + cc] =
                __floats2half2_rn(d1 * acc[ni][2], d1 * acc[ni][3]);
    }
}

// ---------------- Aggregation 2 + bias + log_softmax ----------------
__global__ void k_agg2_softmax(const float* __restrict__ b2,
                               float* __restrict__ out, int M) {
    int gid  = blockIdx.x * blockDim.x + threadIdx.x;
    int c    = gid >> 5;
    int l    = gid & 31;
    if (c >= M) return;

    bool act = (l < 20);
    float ax = 0.f, ay = 0.f;
    int s0 = g_off[c], s1 = g_off[c + 1];
    for (int i = s0; i < s1; i++) {
        int s = g_esrc[i];
        if (act) {
            float2 f = __half22float2(
                __ldg((const __half2*)(g_y2h + (size_t)s * NC) + l));
            ax += f.x; ay += f.y;
        }
    }
    if (act) {
        float2 f = __half22float2(
            __ldg((const __half2*)(g_y2h + (size_t)c * NC) + l));
        ax += f.x; ay += f.y;
    }
    float d  = g_dinv[c];
    float v0 = act ? (d * ax + __ldg(b2 + 2 * l))     : -3.4e38f;
    float v1 = act ? (d * ay + __ldg(b2 + 2 * l + 1)) : -3.4e38f;

    float m = fmaxf(v0, v1);
#pragma unroll
    for (int o = 16; o; o >>= 1) m = fmaxf(m, __shfl_xor_sync(0xffffffffu, m, o));
    float e = act ? (expf(v0 - m) + expf(v1 - m)) : 0.f;
#pragma unroll
    for (int o = 16; o; o >>= 1) e += __shfl_xor_sync(0xffffffffu, e, o);
    float lse = m + logf(e);

    if (act) {
        out[(size_t)c * NC + 2 * l]     = v0 - lse;
        out[(size_t)c * NC + 2 * l + 1] = v1 - lse;
    }
}

// ---------------- launch ----------------
extern "C" void kernel_launch(void* const* d_in, const int* in_sizes, int n_in,
                              void* d_out, int out_size) {
    const float* x   = (const float*)d_in[0];
    const void*  ei  = d_in[1];               // edge_index: int32 OR int64 (detected)
    const float* W1  = (const float*)d_in[2];
    const float* b1  = (const float*)d_in[3];
    const float* W2  = (const float*)d_in[4];
    const float* b2  = (const float*)d_in[5];
    float*       out = (float*)d_out;

    int M = in_sizes[0] / FIN;   // 100000
    int E = in_sizes[1] / 2;     // 3200000

    int tb = 256;
    int gM = (M + tb - 1) / tb;
    int gE = (E + tb - 1) / tb;

    // setup: zero+detect, degree histogram, weight prep
    k_zero_detect<<<gM, tb>>>(ei, M);
    k_hist<<<gE, tb>>>(ei, E);
    k_wprep<<<(HID * FIN + 255) / 256, 256>>>(W1);
    k_w2prep<<<(NC * HID + 255) / 256, 256>>>(W2);

    // CSR: scan (+dinv) + fill
    int NB = (M + 1023) / 1024;          // 98
    k_scan1<<<NB, 256>>>(M);
    k_scan2<<<1, 128>>>(NB);
    k_scan3<<<gM, tb>>>(M, E);
    k_fill<<<gE, tb>>>(ei, E);

    // layer 1: tensor-core GEMM (mma.sync, dbuf) + CSR gather
    cudaFuncSetAttribute(k_mma_gemm1, cudaFuncAttributeMaxDynamicSharedMemorySize,
                         G1_TOT);
    dim3 g1(2, (M + 127) / 128);         // x = colblock (adjacent -> A reuse in L2)
    k_mma_gemm1<<<g1, 256, G1_TOT>>>(x, M);
    int gW = ((M * 32) + tb - 1) / tb;   // one warp per node
    k_agg1<<<gW, tb>>>(b1, M);

    // layer 2: tensor-core GEMM + fused agg/softmax
    cudaFuncSetAttribute(k_mma_gemm2, cudaFuncAttributeMaxDynamicSharedMemorySize,
                         G2_TOT);
    k_mma_gemm2<<<(M + 127) / 128, 256, G2_TOT>>>(M);
    k_agg2_softmax<<<gW, tb>>>(b2, out, M);
}